// round 7
// baseline (speedup 1.0000x reference)
#include <cuda_runtime.h>
#include <math.h>

#define Bsz    16
#define Sd     4096
#define Hd     2048
#define POOLD  4096
#define SPLITS 64
#define ROWS   64                     // rows per main-pass block
#define RPW    16                     // rows per warp (4 warps/block)
#define SCALE  0.022097086912079608f  // 1/sqrt(2048)
#define EPSV   1e-6f

// ---------------- scratch ----------------
__device__ float g_q[Hd];
__device__ float g_qk[Hd];
__device__ float g_pm[Bsz * SPLITS];
__device__ float g_pl[Bsz * SPLITS];
__device__ float g_pacc[Bsz * SPLITS * Hd];   // 8.4 MB
__device__ float g_xp[Bsz * Hd];
__device__ float g_pooled[Bsz * Hd];
__device__ float g_normed[Bsz * Hd];

// ---------------- 1. q[d] = dot(Wq[d,:], lq)  (+ zero-init of atomic targets) ----------------
__global__ void qproj_kernel(const float* __restrict__ Wq,
                             const float* __restrict__ lq,
                             float* __restrict__ out) {
    int gi = blockIdx.x * 256 + threadIdx.x;   // 65536 threads
    if (gi < Hd)        g_qk[gi] = 0.f;
    if (gi < Bsz * Hd)  g_pooled[gi] = 0.f;
    out[gi] = 0.f;

    int d    = blockIdx.x * 8 + (threadIdx.x >> 5);
    int lane = threadIdx.x & 31;
    const float4* r4 = (const float4*)(Wq + (size_t)d * Hd);
    const float4* v4 = (const float4*)lq;
    float s0 = 0.f, s1 = 0.f;
#pragma unroll
    for (int i = 0; i < 16; i += 2) {
        float4 a = r4[lane + 32 * i];
        float4 b = v4[lane + 32 * i];
        s0 += a.x * b.x + a.y * b.y + a.z * b.z + a.w * b.w;
        a = r4[lane + 32 * (i + 1)];
        b = v4[lane + 32 * (i + 1)];
        s1 += a.x * b.x + a.y * b.y + a.z * b.z + a.w * b.w;
    }
    float s = s0 + s1;
#pragma unroll
    for (int o = 16; o; o >>= 1) s += __shfl_xor_sync(0xffffffffu, s, o);
    if (lane == 0) g_q[d] = s;
}

// ---------------- 2. qk[h] += sum_d Wk[d,h] * q[d]   (split-d + atomics) ----------------
__global__ void kproj_kernel(const float* __restrict__ Wk) {
    int h  = blockIdx.x * 256 + threadIdx.x;
    int d0 = blockIdx.y * 64;
    float a0 = 0.f, a1 = 0.f;
#pragma unroll 8
    for (int d = 0; d < 64; d += 2) {
        a0 += Wk[(size_t)(d0 + d) * Hd + h] * g_q[d0 + d];
        a1 += Wk[(size_t)(d0 + d + 1) * Hd + h] * g_q[d0 + d + 1];
    }
    atomicAdd(&g_qk[h], a0 + a1);
}

// ---------------- 3. main flash pass (warp-per-row, smem-staged x) ----------------
// grid = (SPLITS, Bsz), 128 threads = 4 warps, 16 rows each.
// Dot pass streams x from DRAM while staging it to a per-warp smem buffer;
// accumulate pass re-reads from smem. Cuts 64 regs -> 5 blocks/SM.
__global__ void __launch_bounds__(128, 5)
main_pass(const float* __restrict__ X, const int* __restrict__ mask) {
    __shared__ float4 s_stage[4][512];   // 32 KB; also merge buffers at the end
    __shared__ float4 s_qk[512];         // 8 KB
    __shared__ float s_m[4], s_l[4];
    int b = blockIdx.y, sp = blockIdx.x;
    int t = threadIdx.x, lane = t & 31, warp = t >> 5;

    const float4* qk4 = (const float4*)g_qk;
    for (int i = t; i < 512; i += 128) s_qk[i] = qk4[i];

    // prefetch the 16 mask words -> bitmask
    const int4* m4 = (const int4*)(mask + (size_t)b * Sd + sp * ROWS + warp * RPW);
    int4 ma = m4[0], mb = m4[1], mc = m4[2], md = m4[3];
    unsigned mbits = 0;
    mbits |= (ma.x != 0) << 0;  mbits |= (ma.y != 0) << 1;
    mbits |= (ma.z != 0) << 2;  mbits |= (ma.w != 0) << 3;
    mbits |= (mb.x != 0) << 4;  mbits |= (mb.y != 0) << 5;
    mbits |= (mb.z != 0) << 6;  mbits |= (mb.w != 0) << 7;
    mbits |= (mc.x != 0) << 8;  mbits |= (mc.y != 0) << 9;
    mbits |= (mc.z != 0) << 10; mbits |= (mc.w != 0) << 11;
    mbits |= (md.x != 0) << 12; mbits |= (md.y != 0) << 13;
    mbits |= (md.z != 0) << 14; mbits |= (md.w != 0) << 15;
    __syncthreads();

    float m = -INFINITY, l = 0.f;
    float4 acc[16];
#pragma unroll
    for (int i = 0; i < 16; i++) acc[i] = make_float4(0.f, 0.f, 0.f, 0.f);

    const float4* X4 = (const float4*)(X + ((size_t)b * Sd + (size_t)sp * ROWS + warp * RPW) * Hd);
    float4* st = s_stage[warp];

    for (int r = 0; r < RPW; r++) {
        if (!((mbits >> r) & 1u)) continue;   // masked row: weight exactly 0, skip the read
        const float4* xr = X4 + (size_t)r * 512 + lane;
        float px = 0.f, py = 0.f, pz = 0.f, pw = 0.f;
#pragma unroll
        for (int i = 0; i < 16; i++) {
            float4 x = xr[32 * i];            // DRAM read (once)
            st[lane + 32 * i] = x;            // stage to smem
            float4 q = s_qk[lane + 32 * i];
            px += x.x * q.x; py += x.y * q.y;
            pz += x.z * q.z; pw += x.w * q.w;
        }
        float p = (px + py) + (pz + pw);
#pragma unroll
        for (int o = 16; o; o >>= 1) p += __shfl_xor_sync(0xffffffffu, p, o);
        float score = p * SCALE;

        if (score > m) {                      // warp-uniform; rare after first rows
            float c = __expf(m - score);      // exact 0 on first active row
            l *= c;
#pragma unroll
            for (int i = 0; i < 16; i++) {
                acc[i].x *= c; acc[i].y *= c; acc[i].z *= c; acc[i].w *= c;
            }
            m = score;
        }
        float p2 = __expf(score - m);
        l += p2;
#pragma unroll
        for (int i = 0; i < 16; i++) {        // re-read from smem (on-chip, conflict-free)
            float4 x = st[lane + 32 * i];
            acc[i].x += p2 * x.x; acc[i].y += p2 * x.y;
            acc[i].z += p2 * x.z; acc[i].w += p2 * x.w;
        }
    }

    if (lane == 0) { s_m[warp] = m; s_l[warp] = l; }
    __syncthreads();
    float M = fmaxf(fmaxf(s_m[0], s_m[1]), fmaxf(s_m[2], s_m[3]));
    float e = (m == -INFINITY) ? 0.f : __expf(m - M);
#pragma unroll
    for (int i = 0; i < 16; i++) {            // overwrite staging with merge data
        float4 v = acc[i];
        v.x *= e; v.y *= e; v.z *= e; v.w *= e;
        st[lane + 32 * i] = v;
    }
    __syncthreads();
    if (t == 0) {
        float lt = 0.f;
#pragma unroll
        for (int w = 0; w < 4; w++)
            lt += (s_m[w] == -INFINITY) ? 0.f : s_l[w] * __expf(s_m[w] - M);
        g_pm[b * SPLITS + sp] = M;
        g_pl[b * SPLITS + sp] = lt;
    }
    float4* pa = (float4*)(g_pacc + (size_t)(b * SPLITS + sp) * Hd);
    for (int i = t; i < 512; i += 128) {
        float4 a = s_stage[0][i], v1 = s_stage[1][i], v2 = s_stage[2][i], v3 = s_stage[3][i];
        a.x += v1.x + v2.x + v3.x; a.y += v1.y + v2.y + v3.y;
        a.z += v1.z + v2.z + v3.z; a.w += v1.w + v2.w + v3.w;
        pa[i] = a;
    }
}

// ---------------- 4. combine partials -> xp (8 threads per element, tree reduce) ----------------
// grid = (Bsz, 16), 256 threads. Block covers 32 float4 indices; group grp
// (0..7) of 32 threads sums splits [grp*8, grp*8+8); smem tree-reduce.
__global__ void combine_kernel() {
    __shared__ float s_ew[SPLITS];
    __shared__ float s_inv;
    __shared__ float4 s_part[7][32];
    int b = blockIdx.x;
    int t = threadIdx.x;
    if (t < 32) {
        float m0 = g_pm[b * SPLITS + t];
        float m1 = g_pm[b * SPLITS + 32 + t];
        float M = fmaxf(m0, m1);
#pragma unroll
        for (int o = 16; o; o >>= 1) M = fmaxf(M, __shfl_xor_sync(0xffffffffu, M, o));
        float e0 = (m0 == -INFINITY) ? 0.f : __expf(m0 - M);
        float e1 = (m1 == -INFINITY) ? 0.f : __expf(m1 - M);
        float s = g_pl[b * SPLITS + t] * e0 + g_pl[b * SPLITS + 32 + t] * e1;
#pragma unroll
        for (int o = 16; o; o >>= 1) s += __shfl_xor_sync(0xffffffffu, s, o);
        s_ew[t] = e0;
        s_ew[t + 32] = e1;
        if (t == 0) s_inv = 1.f / s;
    }
    __syncthreads();

    int li  = t & 31;                      // local float4 index
    int grp = t >> 5;                      // split group 0..7
    int idx = blockIdx.y * 32 + li;        // float4 index in [0,512)

    float4 s = make_float4(0.f, 0.f, 0.f, 0.f);
    const float4* pa = (const float4*)g_pacc;
#pragma unroll
    for (int i = 0; i < 8; i++) {          // 8 independent loads
        int spl = grp * 8 + i;
        float e = s_ew[spl];
        float4 v = pa[(size_t)(b * SPLITS + spl) * 512 + idx];
        s.x += e * v.x; s.y += e * v.y; s.z += e * v.z; s.w += e * v.w;
    }
    if (grp) s_part[grp - 1][li] = s;
    __syncthreads();
    if (grp == 0) {
        float inv = s_inv;
#pragma unroll
        for (int g = 0; g < 7; g++) {
            float4 p = s_part[g][li];
            s.x += p.x; s.y += p.y; s.z += p.z; s.w += p.w;
        }
        s.x *= inv; s.y *= inv; s.z *= inv; s.w *= inv;
        ((float4*)(g_xp + (size_t)b * Hd))[idx] = s;
    }
}

// ---------------- 5./7. skinny GEMM: out[b,d] += sum_k W[d,k]*xin[b,k] ----------------
__global__ void skinny_gemm(const float* __restrict__ W, int mode,
                            float* __restrict__ dout, int D, int K) {
    __shared__ float ws[64][65];
    __shared__ float xs[16][65];
    const float* xin = (mode == 0) ? g_xp : g_normed;
    float* out       = (mode == 0) ? g_pooled : dout;

    int t  = threadIdx.x;
    int d0 = blockIdx.x * 64;
    int kchunk = K / gridDim.y;
    int k0 = blockIdx.y * kchunk;
    int b0 = (t & 7) * 2;
    int dg = t >> 3;

    float acc[4][2] = {{0.f,0.f},{0.f,0.f},{0.f,0.f},{0.f,0.f}};

    for (int kc = k0; kc < k0 + kchunk; kc += 64) {
        for (int i = t; i < 1024; i += 128) {
            int row = i >> 4, c4 = i & 15;
            float4 v = *(const float4*)&W[(size_t)(d0 + row) * K + kc + c4 * 4];
            ws[row][c4 * 4 + 0] = v.x; ws[row][c4 * 4 + 1] = v.y;
            ws[row][c4 * 4 + 2] = v.z; ws[row][c4 * 4 + 3] = v.w;
        }
        for (int i = t; i < 256; i += 128) {
            int row = i >> 4, c4 = i & 15;
            float4 v = *(const float4*)&xin[(size_t)row * K + kc + c4 * 4];
            xs[row][c4 * 4 + 0] = v.x; xs[row][c4 * 4 + 1] = v.y;
            xs[row][c4 * 4 + 2] = v.z; xs[row][c4 * 4 + 3] = v.w;
        }
        __syncthreads();
#pragma unroll 8
        for (int kt = 0; kt < 64; kt++) {
            float x0 = xs[b0][kt], x1 = xs[b0 + 1][kt];
#pragma unroll
            for (int r = 0; r < 4; r++) {
                float w = ws[dg * 4 + r][kt];
                acc[r][0] += w * x0;
                acc[r][1] += w * x1;
            }
        }
        __syncthreads();
    }
#pragma unroll
    for (int r = 0; r < 4; r++) {
        atomicAdd(&out[(size_t)(b0 + 0) * D + d0 + dg * 4 + r], acc[r][0]);
        atomicAdd(&out[(size_t)(b0 + 1) * D + d0 + dg * 4 + r], acc[r][1]);
    }
}

// ---------------- 6. rmsnorm ----------------
__global__ void rmsnorm_kernel(const float* __restrict__ nw) {
    __shared__ float red[8];
    __shared__ float sv;
    int b = blockIdx.x, t = threadIdx.x, lane = t & 31, warp = t >> 5;
    const float4* p4 = (const float4*)(g_pooled + (size_t)b * Hd);
    float4 v0 = p4[t], v1 = p4[t + 256];
    float ss = v0.x*v0.x + v0.y*v0.y + v0.z*v0.z + v0.w*v0.w
             + v1.x*v1.x + v1.y*v1.y + v1.z*v1.z + v1.w*v1.w;
#pragma unroll
    for (int o = 16; o; o >>= 1) ss += __shfl_xor_sync(0xffffffffu, ss, o);
    if (lane == 0) red[warp] = ss;
    __syncthreads();
    if (t == 0) {
        float s = 0.f;
#pragma unroll
        for (int w = 0; w < 8; w++) s += red[w];
        sv = rsqrtf(s / (float)Hd + EPSV);
    }
    __syncthreads();
    float rs = sv;
    const float4* w4 = (const float4*)nw;
    float4* n4 = (float4*)(g_normed + (size_t)b * Hd);
    float4 wa = w4[t], wb = w4[t + 256];
    float4 o0, o1;
    o0.x = v0.x * rs * wa.x; o0.y = v0.y * rs * wa.y;
    o0.z = v0.z * rs * wa.z; o0.w = v0.w * rs * wa.w;
    o1.x = v1.x * rs * wb.x; o1.y = v1.y * rs * wb.y;
    o1.z = v1.z * rs * wb.z; o1.w = v1.w * rs * wb.w;
    n4[t] = o0;
    n4[t + 256] = o1;
}

// ---------------- launch ----------------
extern "C" void kernel_launch(void* const* d_in, const int* in_sizes, int n_in,
                              void* d_out, int out_size) {
    const float* X  = (const float*)d_in[0];
    const int*   mk = (const int*)d_in[1];
    const float* lq = (const float*)d_in[2];
    const float* Wq = (const float*)d_in[3];
    const float* Wk = (const float*)d_in[4];
    const float* Wv = (const float*)d_in[5];
    const float* Wo = (const float*)d_in[6];
    const float* nw = (const float*)d_in[7];
    float* out = (float*)d_out;

    qproj_kernel<<<Hd / 8, 256>>>(Wq, lq, out);              // q = Wq @ lq  (+ zero init)
    kproj_kernel<<<dim3(Hd / 256, 32), 256>>>(Wk);           // qk = Wk^T q  (split-d + atomics)
    main_pass<<<dim3(SPLITS, Bsz), 128>>>(X, mk);            // online softmax over X
    combine_kernel<<<dim3(Bsz, 16), 256>>>();                // stats + merge splits -> xp
    skinny_gemm<<<dim3(Hd / 64, 16), 128>>>(Wv, 0, out, Hd, Hd);       // pooled = xp @ Wv^T
    rmsnorm_kernel<<<Bsz, 256>>>(nw);                        // normed
    skinny_gemm<<<dim3(POOLD / 64, 16), 128>>>(Wo, 1, out, POOLD, Hd); // out = normed @ Wo^T
}

// round 10
// speedup vs baseline: 1.4283x; 1.4283x over previous
#include <cuda_runtime.h>
#include <math.h>

#define Bsz    16
#define Sd     4096
#define Hd     2048
#define POOLD  4096
#define SPLITS 64
#define ROWS   64                     // rows per main-pass block
#define SCALE  0.022097086912079608f  // 1/sqrt(2048)
#define EPSV   1e-6f

// ---------------- scratch ----------------
__device__ float g_q[Hd];
__device__ float g_qk[Hd];
__device__ float g_pm[Bsz * SPLITS];
__device__ float g_pl[Bsz * SPLITS];
__device__ float g_pacc[Bsz * SPLITS * Hd];   // 8.4 MB
__device__ float g_xp[Bsz * Hd];
__device__ float g_pooled[Bsz * Hd];
__device__ float g_normed[Bsz * Hd];

// ---------------- 1. q[d] = dot(Wq[d,:], lq)  (+ zero-init of atomic targets) ----------------
__global__ void qproj_kernel(const float* __restrict__ Wq,
                             const float* __restrict__ lq,
                             float* __restrict__ out) {
    int gi = blockIdx.x * 256 + threadIdx.x;   // 65536 threads
    if (gi < Hd)        g_qk[gi] = 0.f;
    if (gi < Bsz * Hd)  g_pooled[gi] = 0.f;
    out[gi] = 0.f;

    int d    = blockIdx.x * 8 + (threadIdx.x >> 5);
    int lane = threadIdx.x & 31;
    const float4* r4 = (const float4*)(Wq + (size_t)d * Hd);
    const float4* v4 = (const float4*)lq;
    float s0 = 0.f, s1 = 0.f;
#pragma unroll
    for (int i = 0; i < 16; i += 2) {
        float4 a = r4[lane + 32 * i];
        float4 b = v4[lane + 32 * i];
        s0 += a.x * b.x + a.y * b.y + a.z * b.z + a.w * b.w;
        a = r4[lane + 32 * (i + 1)];
        b = v4[lane + 32 * (i + 1)];
        s1 += a.x * b.x + a.y * b.y + a.z * b.z + a.w * b.w;
    }
    float s = s0 + s1;
#pragma unroll
    for (int o = 16; o; o >>= 1) s += __shfl_xor_sync(0xffffffffu, s, o);
    if (lane == 0) g_q[d] = s;
}

// ---------------- 2. qk[h] += sum_d Wk[d,h] * q[d]   (split-d + atomics) ----------------
__global__ void kproj_kernel(const float* __restrict__ Wk) {
    int h  = blockIdx.x * 256 + threadIdx.x;
    int d0 = blockIdx.y * 64;
    float a0 = 0.f, a1 = 0.f;
#pragma unroll 8
    for (int d = 0; d < 64; d += 2) {
        a0 += Wk[(size_t)(d0 + d) * Hd + h] * g_q[d0 + d];
        a1 += Wk[(size_t)(d0 + d + 1) * Hd + h] * g_q[d0 + d + 1];
    }
    atomicAdd(&g_qk[h], a0 + a1);
}

// ---------------- 3. main flash pass (warp-per-row, x register-buffered, balanced rows) ----------------
// grid = (SPLITS, Bsz), 128 threads = 4 warps. Block builds the active-row
// list once (deterministic order), then warp w takes entries w, w+4, w+8, ...
// Body identical to the proven R6 kernel.
__global__ void __launch_bounds__(128, 3)
main_pass(const float* __restrict__ X, const int* __restrict__ mask) {
    __shared__ float4 sbuf[4][512];   // sbuf[0] = qk during loop; all 4 = merge buffers after
    __shared__ float s_m[4], s_l[4];
    __shared__ int s_am[ROWS];
    __shared__ int s_list[ROWS];
    __shared__ int s_n;
    int b = blockIdx.y, sp = blockIdx.x;
    int t = threadIdx.x, lane = t & 31, warp = t >> 5;

    const float4* qk4 = (const float4*)g_qk;
    for (int i = t; i < 512; i += 128) sbuf[0][i] = qk4[i];

    const int* mk = mask + (size_t)b * Sd + sp * ROWS;
    if (t < ROWS) s_am[t] = mk[t];
    __syncthreads();
    if (t == 0) {                          // deterministic compact (row order preserved)
        int n = 0;
        for (int r = 0; r < ROWS; r++)
            if (s_am[r]) s_list[n++] = r;
        s_n = n;
    }
    __syncthreads();
    int n = s_n;

    float m = -INFINITY, l = 0.f;
    float4 acc[16];
#pragma unroll
    for (int i = 0; i < 16; i++) acc[i] = make_float4(0.f, 0.f, 0.f, 0.f);

    const float4* X4 = (const float4*)(X + ((size_t)b * Sd + (size_t)sp * ROWS) * Hd);

    for (int j = warp; j < n; j += 4) {    // balanced round-robin over active rows
        int r = s_list[j];
        float4 x[16];
#pragma unroll
        for (int i = 0; i < 16; i++) x[i] = X4[(size_t)r * 512 + lane + 32 * i];
        // 4 independent partial chains
        float px = 0.f, py = 0.f, pz = 0.f, pw = 0.f;
#pragma unroll
        for (int i = 0; i < 16; i++) {
            float4 q = sbuf[0][lane + 32 * i];
            px += x[i].x * q.x; py += x[i].y * q.y;
            pz += x[i].z * q.z; pw += x[i].w * q.w;
        }
        float p = (px + py) + (pz + pw);
#pragma unroll
        for (int o = 16; o; o >>= 1) p += __shfl_xor_sync(0xffffffffu, p, o);
        float score = p * SCALE;

        if (score > m) {                   // warp-uniform; rare after first rows
            float c = __expf(m - score);   // exact 0 on first active row
            l *= c;
#pragma unroll
            for (int i = 0; i < 16; i++) {
                acc[i].x *= c; acc[i].y *= c; acc[i].z *= c; acc[i].w *= c;
            }
            m = score;
        }
        float p2 = __expf(score - m);
        l += p2;
#pragma unroll
        for (int i = 0; i < 16; i++) {
            acc[i].x += p2 * x[i].x; acc[i].y += p2 * x[i].y;
            acc[i].z += p2 * x[i].z; acc[i].w += p2 * x[i].w;
        }
    }

    if (lane == 0) { s_m[warp] = m; s_l[warp] = l; }
    __syncthreads();                       // also: done reading qk from sbuf[0]
    float M = fmaxf(fmaxf(s_m[0], s_m[1]), fmaxf(s_m[2], s_m[3]));
    float e = (m == -INFINITY) ? 0.f : __expf(m - M);
#pragma unroll
    for (int i = 0; i < 16; i++) {
        float4 v = acc[i];
        v.x *= e; v.y *= e; v.z *= e; v.w *= e;
        sbuf[warp][lane + 32 * i] = v;
    }
    __syncthreads();
    if (t == 0) {
        float lt = 0.f;
#pragma unroll
        for (int w = 0; w < 4; w++)
            lt += (s_m[w] == -INFINITY) ? 0.f : s_l[w] * __expf(s_m[w] - M);
        g_pm[b * SPLITS + sp] = M;
        g_pl[b * SPLITS + sp] = lt;
    }
    float4* pa = (float4*)(g_pacc + (size_t)(b * SPLITS + sp) * Hd);
    for (int i = t; i < 512; i += 128) {
        float4 a = sbuf[0][i], v1 = sbuf[1][i], v2 = sbuf[2][i], v3 = sbuf[3][i];
        a.x += v1.x + v2.x + v3.x; a.y += v1.y + v2.y + v3.y;
        a.z += v1.z + v2.z + v3.z; a.w += v1.w + v2.w + v3.w;
        pa[i] = a;
    }
}

// ---------------- 4. combine partials -> xp (8 threads per element, tree reduce) ----------------
// grid = (Bsz, 16), 256 threads. Block covers 32 float4 indices; group grp
// (0..7) of 32 threads sums splits [grp*8, grp*8+8); smem tree-reduce.
__global__ void combine_kernel() {
    __shared__ float s_ew[SPLITS];
    __shared__ float s_inv;
    __shared__ float4 s_part[7][32];
    int b = blockIdx.x;
    int t = threadIdx.x;
    if (t < 32) {
        float m0 = g_pm[b * SPLITS + t];
        float m1 = g_pm[b * SPLITS + 32 + t];
        float M = fmaxf(m0, m1);
#pragma unroll
        for (int o = 16; o; o >>= 1) M = fmaxf(M, __shfl_xor_sync(0xffffffffu, M, o));
        float e0 = (m0 == -INFINITY) ? 0.f : __expf(m0 - M);
        float e1 = (m1 == -INFINITY) ? 0.f : __expf(m1 - M);
        float s = g_pl[b * SPLITS + t] * e0 + g_pl[b * SPLITS + 32 + t] * e1;
#pragma unroll
        for (int o = 16; o; o >>= 1) s += __shfl_xor_sync(0xffffffffu, s, o);
        s_ew[t] = e0;
        s_ew[t + 32] = e1;
        if (t == 0) s_inv = 1.f / s;
    }
    __syncthreads();

    int li  = t & 31;                      // local float4 index
    int grp = t >> 5;                      // split group 0..7
    int idx = blockIdx.y * 32 + li;        // float4 index in [0,512)

    float4 s = make_float4(0.f, 0.f, 0.f, 0.f);
    const float4* pa = (const float4*)g_pacc;
#pragma unroll
    for (int i = 0; i < 8; i++) {          // 8 independent loads
        int spl = grp * 8 + i;
        float e = s_ew[spl];
        float4 v = pa[(size_t)(b * SPLITS + spl) * 512 + idx];
        s.x += e * v.x; s.y += e * v.y; s.z += e * v.z; s.w += e * v.w;
    }
    if (grp) s_part[grp - 1][li] = s;
    __syncthreads();
    if (grp == 0) {
        float inv = s_inv;
#pragma unroll
        for (int g = 0; g < 7; g++) {
            float4 p = s_part[g][li];
            s.x += p.x; s.y += p.y; s.z += p.z; s.w += p.w;
        }
        s.x *= inv; s.y *= inv; s.z *= inv; s.w *= inv;
        ((float4*)(g_xp + (size_t)b * Hd))[idx] = s;
    }
}

// ---------------- 5./7. skinny GEMM: out[b,d] += sum_k W[d,k]*xin[b,k] ----------------
__global__ void skinny_gemm(const float* __restrict__ W, int mode,
                            float* __restrict__ dout, int D, int K) {
    __shared__ float ws[64][65];
    __shared__ float xs[16][65];
    const float* xin = (mode == 0) ? g_xp : g_normed;
    float* out       = (mode == 0) ? g_pooled : dout;

    int t  = threadIdx.x;
    int d0 = blockIdx.x * 64;
    int kchunk = K / gridDim.y;
    int k0 = blockIdx.y * kchunk;
    int b0 = (t & 7) * 2;
    int dg = t >> 3;

    float acc[4][2] = {{0.f,0.f},{0.f,0.f},{0.f,0.f},{0.f,0.f}};

    for (int kc = k0; kc < k0 + kchunk; kc += 64) {
        for (int i = t; i < 1024; i += 128) {
            int row = i >> 4, c4 = i & 15;
            float4 v = *(const float4*)&W[(size_t)(d0 + row) * K + kc + c4 * 4];
            ws[row][c4 * 4 + 0] = v.x; ws[row][c4 * 4 + 1] = v.y;
            ws[row][c4 * 4 + 2] = v.z; ws[row][c4 * 4 + 3] = v.w;
        }
        for (int i = t; i < 256; i += 128) {
            int row = i >> 4, c4 = i & 15;
            float4 v = *(const float4*)&xin[(size_t)row * K + kc + c4 * 4];
            xs[row][c4 * 4 + 0] = v.x; xs[row][c4 * 4 + 1] = v.y;
            xs[row][c4 * 4 + 2] = v.z; xs[row][c4 * 4 + 3] = v.w;
        }
        __syncthreads();
#pragma unroll 8
        for (int kt = 0; kt < 64; kt++) {
            float x0 = xs[b0][kt], x1 = xs[b0 + 1][kt];
#pragma unroll
            for (int r = 0; r < 4; r++) {
                float w = ws[dg * 4 + r][kt];
                acc[r][0] += w * x0;
                acc[r][1] += w * x1;
            }
        }
        __syncthreads();
    }
#pragma unroll
    for (int r = 0; r < 4; r++) {
        atomicAdd(&out[(size_t)(b0 + 0) * D + d0 + dg * 4 + r], acc[r][0]);
        atomicAdd(&out[(size_t)(b0 + 1) * D + d0 + dg * 4 + r], acc[r][1]);
    }
}

// ---------------- 6. rmsnorm ----------------
__global__ void rmsnorm_kernel(const float* __restrict__ nw) {
    __shared__ float red[8];
    __shared__ float sv;
    int b = blockIdx.x, t = threadIdx.x, lane = t & 31, warp = t >> 5;
    const float4* p4 = (const float4*)(g_pooled + (size_t)b * Hd);
    float4 v0 = p4[t], v1 = p4[t + 256];
    float ss = v0.x*v0.x + v0.y*v0.y + v0.z*v0.z + v0.w*v0.w
             + v1.x*v1.x + v1.y*v1.y + v1.z*v1.z + v1.w*v1.w;
#pragma unroll
    for (int o = 16; o; o >>= 1) ss += __shfl_xor_sync(0xffffffffu, ss, o);
    if (lane == 0) red[warp] = ss;
    __syncthreads();
    if (t == 0) {
        float s = 0.f;
#pragma unroll
        for (int w = 0; w < 8; w++) s += red[w];
        sv = rsqrtf(s / (float)Hd + EPSV);
    }
    __syncthreads();
    float rs = sv;
    const float4* w4 = (const float4*)nw;
    float4* n4 = (float4*)(g_normed + (size_t)b * Hd);
    float4 wa = w4[t], wb = w4[t + 256];
    float4 o0, o1;
    o0.x = v0.x * rs * wa.x; o0.y = v0.y * rs * wa.y;
    o0.z = v0.z * rs * wa.z; o0.w = v0.w * rs * wa.w;
    o1.x = v1.x * rs * wb.x; o1.y = v1.y * rs * wb.y;
    o1.z = v1.z * rs * wb.z; o1.w = v1.w * rs * wb.w;
    n4[t] = o0;
    n4[t + 256] = o1;
}

// ---------------- launch ----------------
extern "C" void kernel_launch(void* const* d_in, const int* in_sizes, int n_in,
                              void* d_out, int out_size) {
    const float* X  = (const float*)d_in[0];
    const int*   mk = (const int*)d_in[1];
    const float* lq = (const float*)d_in[2];
    const float* Wq = (const float*)d_in[3];
    const float* Wk = (const float*)d_in[4];
    const float* Wv = (const float*)d_in[5];
    const float* Wo = (const float*)d_in[6];
    const float* nw = (const float*)d_in[7];
    float* out = (float*)d_out;

    qproj_kernel<<<Hd / 8, 256>>>(Wq, lq, out);              // q = Wq @ lq  (+ zero init)
    kproj_kernel<<<dim3(Hd / 256, 32), 256>>>(Wk);           // qk = Wk^T q  (split-d + atomics)
    main_pass<<<dim3(SPLITS, Bsz), 128>>>(X, mk);            // online softmax over X (balanced)
    combine_kernel<<<dim3(Bsz, 16), 256>>>();                // stats + merge splits -> xp
    skinny_gemm<<<dim3(Hd / 64, 16), 128>>>(Wv, 0, out, Hd, Hd);       // pooled = xp @ Wv^T
    rmsnorm_kernel<<<Bsz, 256>>>(nw);                        // normed
    skinny_gemm<<<dim3(POOLD / 64, 16), 128>>>(Wo, 1, out, POOLD, Hd); // out = normed @ Wo^T
}

// round 11
// speedup vs baseline: 1.6261x; 1.1385x over previous
#include <cuda_runtime.h>
#include <math.h>

#define Bsz    16
#define Sd     4096
#define Hd     2048
#define POOLD  4096
#define SPLITS 64
#define ROWS   64                     // rows per main-pass block
#define RPW    16                     // rows per warp (4 warps/block)
#define SCALE  0.022097086912079608f  // 1/sqrt(2048)
#define EPSV   1e-6f

#define PF_L2(p) asm volatile("prefetch.global.L2 [%0];" :: "l"(p))

// ---------------- scratch ----------------
__device__ float g_q[Hd];
__device__ float g_qk[Hd];
__device__ float g_pm[Bsz * SPLITS];
__device__ float g_pl[Bsz * SPLITS];
__device__ float g_pacc[Bsz * SPLITS * Hd];   // 8.4 MB
__device__ float g_xp[Bsz * Hd];
__device__ float g_pooled[Bsz * Hd];
__device__ float g_normed[Bsz * Hd];

// ---------------- 0. zero init (atomic targets) ----------------
__global__ void zero_kernel(float* __restrict__ out) {
    int i = blockIdx.x * 256 + threadIdx.x;   // 65536 threads
    if (i < Hd)        g_qk[i] = 0.f;
    if (i < Bsz * Hd)  g_pooled[i] = 0.f;
    out[i] = 0.f;
}

// ---------------- 1. q[d] = dot(Wq[d,:], lq) ----------------
__global__ void qproj_kernel(const float* __restrict__ Wq,
                             const float* __restrict__ lq) {
    int d    = blockIdx.x * 8 + (threadIdx.x >> 5);
    int lane = threadIdx.x & 31;
    const float4* r4 = (const float4*)(Wq + (size_t)d * Hd);
    const float4* v4 = (const float4*)lq;
    float s0 = 0.f, s1 = 0.f;
#pragma unroll
    for (int i = 0; i < 16; i += 2) {
        float4 a = r4[lane + 32 * i];
        float4 b = v4[lane + 32 * i];
        s0 += a.x * b.x + a.y * b.y + a.z * b.z + a.w * b.w;
        a = r4[lane + 32 * (i + 1)];
        b = v4[lane + 32 * (i + 1)];
        s1 += a.x * b.x + a.y * b.y + a.z * b.z + a.w * b.w;
    }
    float s = s0 + s1;
#pragma unroll
    for (int o = 16; o; o >>= 1) s += __shfl_xor_sync(0xffffffffu, s, o);
    if (lane == 0) g_q[d] = s;
}

// ---------------- 2. qk[h] += sum_d Wk[d,h] * q[d]   (split-d + atomics) ----------------
__global__ void kproj_kernel(const float* __restrict__ Wk) {
    int h  = blockIdx.x * 256 + threadIdx.x;
    int d0 = blockIdx.y * 64;
    float a0 = 0.f, a1 = 0.f;
#pragma unroll 8
    for (int d = 0; d < 64; d += 2) {
        a0 += Wk[(size_t)(d0 + d) * Hd + h] * g_q[d0 + d];
        a1 += Wk[(size_t)(d0 + d + 1) * Hd + h] * g_q[d0 + d + 1];
    }
    atomicAdd(&g_qk[h], a0 + a1);
}

// ---------------- 3. main flash pass (R6 body + L2 prefetch of row r+2) ----------------
// grid = (SPLITS, Bsz), 128 threads = 4 warps, 16 fixed rows each.
__global__ void __launch_bounds__(128, 3)
main_pass(const float* __restrict__ X, const int* __restrict__ mask) {
    __shared__ float4 sbuf[4][512];   // sbuf[0] = qk during loop; all 4 = merge buffers after
    __shared__ float s_m[4], s_l[4];
    int b = blockIdx.y, sp = blockIdx.x;
    int t = threadIdx.x, lane = t & 31, warp = t >> 5;

    const float4* qk4 = (const float4*)g_qk;
    for (int i = t; i < 512; i += 128) sbuf[0][i] = qk4[i];

    // prefetch the 16 mask words -> bitmask
    const int4* m4 = (const int4*)(mask + (size_t)b * Sd + sp * ROWS + warp * RPW);
    int4 ma = m4[0], mb = m4[1], mc = m4[2], md = m4[3];
    unsigned mbits = 0;
    mbits |= (ma.x != 0) << 0;  mbits |= (ma.y != 0) << 1;
    mbits |= (ma.z != 0) << 2;  mbits |= (ma.w != 0) << 3;
    mbits |= (mb.x != 0) << 4;  mbits |= (mb.y != 0) << 5;
    mbits |= (mb.z != 0) << 6;  mbits |= (mb.w != 0) << 7;
    mbits |= (mc.x != 0) << 8;  mbits |= (mc.y != 0) << 9;
    mbits |= (mc.z != 0) << 10; mbits |= (mc.w != 0) << 11;
    mbits |= (md.x != 0) << 12; mbits |= (md.y != 0) << 13;
    mbits |= (md.z != 0) << 14; mbits |= (md.w != 0) << 15;
    __syncthreads();

    float m = -INFINITY, l = 0.f;
    float4 acc[16];
#pragma unroll
    for (int i = 0; i < 16; i++) acc[i] = make_float4(0.f, 0.f, 0.f, 0.f);

    const float4* X4 = (const float4*)(X + ((size_t)b * Sd + (size_t)sp * ROWS + warp * RPW) * Hd);

    // warm the pipe: prefetch first two active rows into L2
    if (mbits & 1u)  { const char* pf = (const char*)X4 + lane * 128;
                       PF_L2(pf); PF_L2(pf + 4096); }
    if (mbits & 2u)  { const char* pf = (const char*)(X4 + 512) + lane * 128;
                       PF_L2(pf); PF_L2(pf + 4096); }

    for (int r = 0; r < RPW; r++) {
        int rp = r + 2;                       // prefetch row r+2 (issued every iter)
        if (rp < RPW && ((mbits >> rp) & 1u)) {
            const char* pf = (const char*)(X4 + (size_t)rp * 512) + lane * 128;
            PF_L2(pf); PF_L2(pf + 4096);
        }
        if (!((mbits >> r) & 1u)) continue;   // masked row: weight exactly 0, skip the read
        float4 x[16];
#pragma unroll
        for (int i = 0; i < 16; i++) x[i] = X4[(size_t)r * 512 + lane + 32 * i];
        // 4 independent partial chains
        float px = 0.f, py = 0.f, pz = 0.f, pw = 0.f;
#pragma unroll
        for (int i = 0; i < 16; i++) {
            float4 q = sbuf[0][lane + 32 * i];
            px += x[i].x * q.x; py += x[i].y * q.y;
            pz += x[i].z * q.z; pw += x[i].w * q.w;
        }
        float p = (px + py) + (pz + pw);
#pragma unroll
        for (int o = 16; o; o >>= 1) p += __shfl_xor_sync(0xffffffffu, p, o);
        float score = p * SCALE;

        if (score > m) {                      // warp-uniform; rare after first rows
            float c = __expf(m - score);      // exact 0 on first active row
            l *= c;
#pragma unroll
            for (int i = 0; i < 16; i++) {
                acc[i].x *= c; acc[i].y *= c; acc[i].z *= c; acc[i].w *= c;
            }
            m = score;
        }
        float p2 = __expf(score - m);
        l += p2;
#pragma unroll
        for (int i = 0; i < 16; i++) {
            acc[i].x += p2 * x[i].x; acc[i].y += p2 * x[i].y;
            acc[i].z += p2 * x[i].z; acc[i].w += p2 * x[i].w;
        }
    }

    if (lane == 0) { s_m[warp] = m; s_l[warp] = l; }
    __syncthreads();                          // also: done reading qk from sbuf[0]
    float M = fmaxf(fmaxf(s_m[0], s_m[1]), fmaxf(s_m[2], s_m[3]));
    float e = (m == -INFINITY) ? 0.f : __expf(m - M);
#pragma unroll
    for (int i = 0; i < 16; i++) {
        float4 v = acc[i];
        v.x *= e; v.y *= e; v.z *= e; v.w *= e;
        sbuf[warp][lane + 32 * i] = v;
    }
    __syncthreads();
    if (t == 0) {
        float lt = 0.f;
#pragma unroll
        for (int w = 0; w < 4; w++)
            lt += (s_m[w] == -INFINITY) ? 0.f : s_l[w] * __expf(s_m[w] - M);
        g_pm[b * SPLITS + sp] = M;
        g_pl[b * SPLITS + sp] = lt;
    }
    float4* pa = (float4*)(g_pacc + (size_t)(b * SPLITS + sp) * Hd);
    for (int i = t; i < 512; i += 128) {
        float4 a = sbuf[0][i], v1 = sbuf[1][i], v2 = sbuf[2][i], v3 = sbuf[3][i];
        a.x += v1.x + v2.x + v3.x; a.y += v1.y + v2.y + v3.y;
        a.z += v1.z + v2.z + v3.z; a.w += v1.w + v2.w + v3.w;
        pa[i] = a;
    }
}

// ---------------- 4. combine partials -> xp (8 threads per element, tree reduce) ----------------
__global__ void combine_kernel() {         // grid = (Bsz, 16), 256 threads
    __shared__ float s_ew[SPLITS];
    __shared__ float s_inv;
    __shared__ float4 s_part[7][32];
    int b = blockIdx.x;
    int t = threadIdx.x;
    if (t < 32) {
        float m0 = g_pm[b * SPLITS + t];
        float m1 = g_pm[b * SPLITS + 32 + t];
        float M = fmaxf(m0, m1);
#pragma unroll
        for (int o = 16; o; o >>= 1) M = fmaxf(M, __shfl_xor_sync(0xffffffffu, M, o));
        float e0 = (m0 == -INFINITY) ? 0.f : __expf(m0 - M);
        float e1 = (m1 == -INFINITY) ? 0.f : __expf(m1 - M);
        float s = g_pl[b * SPLITS + t] * e0 + g_pl[b * SPLITS + 32 + t] * e1;
#pragma unroll
        for (int o = 16; o; o >>= 1) s += __shfl_xor_sync(0xffffffffu, s, o);
        s_ew[t] = e0;
        s_ew[t + 32] = e1;
        if (t == 0) s_inv = 1.f / s;
    }
    __syncthreads();

    int li  = t & 31;                      // local float4 index
    int grp = t >> 5;                      // split group 0..7
    int idx = blockIdx.y * 32 + li;        // float4 index in [0,512)

    float4 s = make_float4(0.f, 0.f, 0.f, 0.f);
    const float4* pa = (const float4*)g_pacc;
#pragma unroll
    for (int i = 0; i < 8; i++) {          // 8 independent loads
        int spl = grp * 8 + i;
        float e = s_ew[spl];
        float4 v = pa[(size_t)(b * SPLITS + spl) * 512 + idx];
        s.x += e * v.x; s.y += e * v.y; s.z += e * v.z; s.w += e * v.w;
    }
    if (grp) s_part[grp - 1][li] = s;
    __syncthreads();
    if (grp == 0) {
        float inv = s_inv;
#pragma unroll
        for (int g = 0; g < 7; g++) {
            float4 p = s_part[g][li];
            s.x += p.x; s.y += p.y; s.z += p.z; s.w += p.w;
        }
        s.x *= inv; s.y *= inv; s.z *= inv; s.w *= inv;
        ((float4*)(g_xp + (size_t)b * Hd))[idx] = s;
    }
}

// ---------------- 5./7. skinny GEMM: out[b,d] += sum_k W[d,k]*xin[b,k] ----------------
__global__ void skinny_gemm(const float* __restrict__ W, int mode,
                            float* __restrict__ dout, int D, int K) {
    __shared__ float ws[64][65];
    __shared__ float xs[16][65];
    const float* xin = (mode == 0) ? g_xp : g_normed;
    float* out       = (mode == 0) ? g_pooled : dout;

    int t  = threadIdx.x;
    int d0 = blockIdx.x * 64;
    int kchunk = K / gridDim.y;
    int k0 = blockIdx.y * kchunk;
    int b0 = (t & 7) * 2;
    int dg = t >> 3;

    float acc[4][2] = {{0.f,0.f},{0.f,0.f},{0.f,0.f},{0.f,0.f}};

    for (int kc = k0; kc < k0 + kchunk; kc += 64) {
        for (int i = t; i < 1024; i += 128) {
            int row = i >> 4, c4 = i & 15;
            float4 v = *(const float4*)&W[(size_t)(d0 + row) * K + kc + c4 * 4];
            ws[row][c4 * 4 + 0] = v.x; ws[row][c4 * 4 + 1] = v.y;
            ws[row][c4 * 4 + 2] = v.z; ws[row][c4 * 4 + 3] = v.w;
        }
        for (int i = t; i < 256; i += 128) {
            int row = i >> 4, c4 = i & 15;
            float4 v = *(const float4*)&xin[(size_t)row * K + kc + c4 * 4];
            xs[row][c4 * 4 + 0] = v.x; xs[row][c4 * 4 + 1] = v.y;
            xs[row][c4 * 4 + 2] = v.z; xs[row][c4 * 4 + 3] = v.w;
        }
        __syncthreads();
#pragma unroll 8
        for (int kt = 0; kt < 64; kt++) {
            float x0 = xs[b0][kt], x1 = xs[b0 + 1][kt];
#pragma unroll
            for (int r = 0; r < 4; r++) {
                float w = ws[dg * 4 + r][kt];
                acc[r][0] += w * x0;
                acc[r][1] += w * x1;
            }
        }
        __syncthreads();
    }
#pragma unroll
    for (int r = 0; r < 4; r++) {
        atomicAdd(&out[(size_t)(b0 + 0) * D + d0 + dg * 4 + r], acc[r][0]);
        atomicAdd(&out[(size_t)(b0 + 1) * D + d0 + dg * 4 + r], acc[r][1]);
    }
}

// ---------------- 6. rmsnorm ----------------
__global__ void rmsnorm_kernel(const float* __restrict__ nw) {
    __shared__ float red[8];
    __shared__ float sv;
    int b = blockIdx.x, t = threadIdx.x, lane = t & 31, warp = t >> 5;
    const float4* p4 = (const float4*)(g_pooled + (size_t)b * Hd);
    float4 v0 = p4[t], v1 = p4[t + 256];
    float ss = v0.x*v0.x + v0.y*v0.y + v0.z*v0.z + v0.w*v0.w
             + v1.x*v1.x + v1.y*v1.y + v1.z*v1.z + v1.w*v1.w;
#pragma unroll
    for (int o = 16; o; o >>= 1) ss += __shfl_xor_sync(0xffffffffu, ss, o);
    if (lane == 0) red[warp] = ss;
    __syncthreads();
    if (t == 0) {
        float s = 0.f;
#pragma unroll
        for (int w = 0; w < 8; w++) s += red[w];
        sv = rsqrtf(s / (float)Hd + EPSV);
    }
    __syncthreads();
    float rs = sv;
    const float4* w4 = (const float4*)nw;
    float4* n4 = (float4*)(g_normed + (size_t)b * Hd);
    float4 wa = w4[t], wb = w4[t + 256];
    float4 o0, o1;
    o0.x = v0.x * rs * wa.x; o0.y = v0.y * rs * wa.y;
    o0.z = v0.z * rs * wa.z; o0.w = v0.w * rs * wa.w;
    o1.x = v1.x * rs * wb.x; o1.y = v1.y * rs * wb.y;
    o1.z = v1.z * rs * wb.z; o1.w = v1.w * rs * wb.w;
    n4[t] = o0;
    n4[t + 256] = o1;
}

// ---------------- launch ----------------
extern "C" void kernel_launch(void* const* d_in, const int* in_sizes, int n_in,
                              void* d_out, int out_size) {
    const float* X  = (const float*)d_in[0];
    const int*   mk = (const int*)d_in[1];
    const float* lq = (const float*)d_in[2];
    const float* Wq = (const float*)d_in[3];
    const float* Wk = (const float*)d_in[4];
    const float* Wv = (const float*)d_in[5];
    const float* Wo = (const float*)d_in[6];
    const float* nw = (const float*)d_in[7];
    float* out = (float*)d_out;

    zero_kernel<<<256, 256>>>(out);                          // zero atomic targets
    qproj_kernel<<<Hd / 8, 256>>>(Wq, lq);                   // q = Wq @ lq
    kproj_kernel<<<dim3(Hd / 256, 32), 256>>>(Wk);           // qk = Wk^T q
    main_pass<<<dim3(SPLITS, Bsz), 128>>>(X, mk);            // online softmax (4th -> profiled)
    combine_kernel<<<dim3(Bsz, 16), 256>>>();                // stats + merge splits -> xp
    skinny_gemm<<<dim3(Hd / 64, 16), 128>>>(Wv, 0, out, Hd, Hd);       // pooled = xp @ Wv^T
    rmsnorm_kernel<<<Bsz, 256>>>(nw);                        // normed
    skinny_gemm<<<dim3(POOLD / 64, 16), 128>>>(Wo, 1, out, POOLD, Hd); // out = normed @ Wo^T
}